// round 8
// baseline (speedup 1.0000x reference)
#include <cuda_runtime.h>
#include <math.h>

#define BB 8
#define CC 64
#define OO 64
#define HH 128
#define WW 128
#define HWSZ (HH*WW)            // 16384
#define NPIX (BB*HWSZ)          // 131072
#define TPB 256

typedef unsigned long long ull;

// ---------------- scratch (allocation-free: __device__ globals) --------------
__device__ float  g_wom_t[CC*9*28];            // [c][t][j] j:0..17 offset,18..26 mask,27 pad
__device__ float  g_Wt[CC*576];                // [c][k*64+o]
__device__ float4 g_cw4[(size_t)NPIX*9];       // per (p,k): 4 corner weights (mask folded)
__device__ int4   g_ci4[(size_t)NPIX*9];       // per (p,k): 4 clamped hw indices
__device__ float  g_xt[(size_t)NPIX*CC];       // x transposed: [b][hw][c]  (33.5 MB, L2-resident)
__device__ float  g_S[(size_t)576*NPIX];       // sampled: [k*64+c][p]  (302 MB)

// ---------------- packed f32x2 helpers ---------------------------------------
__device__ __forceinline__ ull pk2(float lo, float hi){
    ull r; asm("mov.b64 %0, {%1,%2};" : "=l"(r) : "f"(lo), "f"(hi)); return r;
}
__device__ __forceinline__ void upk2(ull v, float& lo, float& hi){
    asm("mov.b64 {%0,%1}, %2;" : "=f"(lo), "=f"(hi) : "l"(v));
}
__device__ __forceinline__ ull f2fma(ull a, ull b, ull c){
    ull d; asm("fma.rn.f32x2 %0, %1, %2, %3;" : "=l"(d) : "l"(a), "l"(b), "l"(c)); return d;
}
__device__ __forceinline__ ull ldg2(const float* p){
    ull v; asm("ld.global.nc.b64 %0, [%1];" : "=l"(v) : "l"(p)); return v;
}

// ---------------- prep: transpose weights ------------------------------------
__global__ void k_prep(const float* __restrict__ wm,
                       const float* __restrict__ wo,
                       const float* __restrict__ wk){
    int i = blockIdx.x*TPB + threadIdx.x;
    if (i < CC*576){                       // g_Wt[c][k*64+o] = wm[o,c,k]
        int c = i/576; int r = i - c*576; int k = r/64; int o = r - k*64;
        g_Wt[i] = wm[(o*CC + c)*9 + k];
    }
    int j2 = i - CC*576;
    if (j2 >= 0 && j2 < CC*9*28){
        int ct = j2/28; int j = j2 - ct*28; int c = ct/9; int t = ct - c*9;
        float v = 0.f;
        if (j < 18)      v = wo[(j*CC + c)*9 + t];
        else if (j < 27) v = wk[((j-18)*CC + c)*9 + t];
        g_wom_t[j2] = v;
    }
}

// ---------------- P0: x [b][c][hw] -> g_xt [b][hw][c] -------------------------
__global__ void k_xt(const float* __restrict__ x){
    __shared__ float t[32][33];
    int b  = blockIdx.z;
    int c0 = blockIdx.y*32;
    int hw0= blockIdx.x*32;
    const float* xb = x + ((size_t)b*CC + c0)*HWSZ + hw0;
    for (int i = threadIdx.y; i < 32; i += 8)
        t[i][threadIdx.x] = xb[(size_t)i*HWSZ + threadIdx.x];   // t[c][hw]
    __syncthreads();
    float* xtb = g_xt + ((size_t)b*HWSZ + hw0)*CC + c0;
    for (int i = threadIdx.y; i < 32; i += 8)
        xtb[(size_t)i*CC + threadIdx.x] = t[threadIdx.x][i];    // [hw][c]
}

// ---- P1: offset(18)+mask(9) 3x3 conv, fused; emit folded corner wgts/idx ----
__global__ void __launch_bounds__(TPB)
k_offmask(const float* __restrict__ x,
          const float* __restrict__ boff,
          const float* __restrict__ bmsk){
    __shared__ __align__(16) float s_wom[32*9*28];   // 31.5 KB

    int p   = blockIdx.x*TPB + threadIdx.x;
    int b   = p >> 14;
    int hw  = p & (HWSZ-1);
    int h   = hw >> 7;
    int wp  = hw & (WW-1);
    const float* xb = x + (size_t)b*CC*HWSZ;

    ull acc[14];
    #pragma unroll
    for (int q=0;q<14;q++){
        int j0=2*q, j1=2*q+1;
        float lo = (j0<18)? boff[j0] : (j0<27 ? bmsk[j0-18] : 0.f);
        float hi = (j1<18)? boff[j1] : (j1<27 ? bmsk[j1-18] : 0.f);
        acc[q] = pk2(lo,hi);
    }

    for (int cc=0; cc<CC; cc+=32){
        __syncthreads();
        for (int i=threadIdx.x; i<32*9*28; i+=TPB)
            s_wom[i] = g_wom_t[cc*9*28 + i];
        __syncthreads();

        for (int c=0;c<32;c++){
            const float* xc = xb + (cc+c)*HWSZ;
            float v[9];
            #pragma unroll
            for (int t=0;t<9;t++){
                int yy = h + t/3 - 1, xx = wp + t%3 - 1;
                v[t] = (yy>=0 && yy<HH && xx>=0 && xx<WW) ? __ldg(xc + yy*WW + xx) : 0.f;
            }
            #pragma unroll
            for (int t=0;t<9;t++){
                ull vv = pk2(v[t], v[t]);
                const ulonglong2* wq = (const ulonglong2*)&s_wom[(c*9+t)*28];
                #pragma unroll
                for (int q=0;q<7;q++){
                    ulonglong2 ww = wq[q];
                    acc[2*q]   = f2fma(vv, ww.x, acc[2*q]);
                    acc[2*q+1] = f2fma(vv, ww.y, acc[2*q+1]);
                }
            }
        }
    }

    #pragma unroll
    for (int k=0;k<9;k++){
        float dy, dx; upk2(acc[k], dy, dx);
        float mlo, mhi; upk2(acc[9 + k/2], mlo, mhi);
        float mraw = (k & 1) ? mhi : mlo;
        float mk = 1.f/(1.f + expf(-mraw));

        float py = dy + (float)(h + k/3 - 1);
        float px = dx + (float)(wp + k%3 - 1);
        float y0f = floorf(py), x0f = floorf(px);
        float ly = py - y0f, lx = px - x0f;
        int y0 = (int)y0f, x0 = (int)x0f;
        int y1 = y0 + 1,   x1 = x0 + 1;

        float vy0 = (y0>=0 && y0<HH) ? 1.f : 0.f;
        float vy1 = (y1>=0 && y1<HH) ? 1.f : 0.f;
        float vx0 = (x0>=0 && x0<WW) ? 1.f : 0.f;
        float vx1 = (x1>=0 && x1<WW) ? 1.f : 0.f;

        float w00 = (1.f-ly)*(1.f-lx)*vy0*vx0*mk;
        float w01 = (1.f-ly)*lx      *vy0*vx1*mk;
        float w10 = ly      *(1.f-lx)*vy1*vx0*mk;
        float w11 = ly      *lx      *vy1*vx1*mk;

        int y0c = min(max(y0,0),HH-1), y1c = min(max(y1,0),HH-1);
        int x0c = min(max(x0,0),WW-1), x1c = min(max(x1,0),WW-1);

        g_cw4[(size_t)p*9 + k] = make_float4(w00,w01,w10,w11);
        g_ci4[(size_t)p*9 + k] = make_int4(y0c*WW+x0c, y0c*WW+x1c,
                                           y1c*WW+x0c, y1c*WW+x1c);
    }
}

// ---- P2: sample: S[k*64+c][p] = sum_corner w(p,k) * x_t[idx][c] -------------
__global__ void __launch_bounds__(TPB)
k_sample(){
    __shared__ float tile[64][33];   // 8.4 KB

    int t  = threadIdx.x, w = t>>5, l = t&31;
    int p0 = blockIdx.x*32;
    int b  = p0 >> 14;
    const float* xtb = g_xt + (size_t)b*HWSZ*CC;

    for (int k=0;k<9;k++){
        __syncthreads();
        #pragma unroll
        for (int j=0;j<4;j++){
            int px = w*4 + j;
            size_t pk = (size_t)(p0+px)*9 + k;
            float4 wq = __ldg(&g_cw4[pk]);
            int4   iq = __ldg(&g_ci4[pk]);
            ull v;
            v = f2fma(pk2(wq.x,wq.x), ldg2(xtb + (size_t)iq.x*CC + 2*l), 0ull);
            v = f2fma(pk2(wq.y,wq.y), ldg2(xtb + (size_t)iq.y*CC + 2*l), v);
            v = f2fma(pk2(wq.z,wq.z), ldg2(xtb + (size_t)iq.z*CC + 2*l), v);
            v = f2fma(pk2(wq.w,wq.w), ldg2(xtb + (size_t)iq.w*CC + 2*l), v);
            float lo,hi; upk2(v,lo,hi);
            tile[2*l  ][px] = lo;
            tile[2*l+1][px] = hi;
        }
        __syncthreads();
        float* Sk = g_S + ((size_t)k*64)*NPIX + p0;
        #pragma unroll
        for (int j=0;j<8;j++){
            int c = w*8 + j;
            Sk[(size_t)c*NPIX + l] = tile[c][l];     // 128B coalesced per row
        }
    }
}

// ---- P3: streaming GEMM  out[p,o] = sum_{k,c} S[k*64+c][p] * Wt[c][k*64+o] --
// CTA = 128 px, K=576 in 9 chunks of 64. NO register prefetch — simple
// sync/load/sync/compute; overlap comes from 3 CTAs/SM.
__global__ void __launch_bounds__(TPB, 3)
k_gemm2(float* __restrict__ out){
    __shared__ __align__(16) float sm[64*128 + 64*64];   // 48 KB
    float* A_s = sm;           // [c][128]
    float* B_s = sm + 8192;    // [c][64]

    int t   = threadIdx.x;
    int p0  = blockIdx.x*128;
    int b   = p0 >> 14;
    int hw0 = p0 & (HWSZ-1);

    int tx = t & 15;     // 4 o  : o = tx*4+q
    int ty = t >> 4;     // 8 px : px pairs ty*8+2j
    ull acc[4][4];
    #pragma unroll
    for (int j=0;j<4;j++){ acc[j][0]=0ull; acc[j][1]=0ull; acc[j][2]=0ull; acc[j][3]=0ull; }

    // per-thread load addresses (fixed across chunks)
    int la_c = 0, la_x = 0;     // A: 8 float4/thread
    int lb_c = t>>4, lb_o = (t&15)*4;  // B wrong shape; recompute below

    for (int kc=0;kc<9;kc++){
        __syncthreads();
        // load A chunk: 64x128 floats, 8 float4 per thread, coalesced rows
        #pragma unroll
        for (int q=0;q<8;q++){
            int fi = q*256+t; int c = fi>>5, x4 = fi&31;
            *(float4*)&A_s[c*128 + x4*4] =
                __ldg((const float4*)(g_S + ((size_t)(kc*64+c))*NPIX + p0 + x4*4));
        }
        // load B chunk: 64x64 floats, 4 float4 per thread
        #pragma unroll
        for (int q=0;q<4;q++){
            int fb = q*256+t; int c = fb>>4, o4 = fb&15;
            *(float4*)&B_s[c*64 + o4*4] = *(const float4*)(g_Wt + c*576 + kc*64 + o4*4);
        }
        __syncthreads();

        #pragma unroll 8
        for (int kk=0; kk<64; kk++){
            ulonglong2 a01 = *(ulonglong2*)&A_s[kk*128 + ty*8];
            ulonglong2 a23 = *(ulonglong2*)&A_s[kk*128 + ty*8+4];
            float4 bv = *(float4*)&B_s[kk*64 + tx*4];
            ull b0 = pk2(bv.x,bv.x), b1 = pk2(bv.y,bv.y);
            ull b2 = pk2(bv.z,bv.z), b3 = pk2(bv.w,bv.w);
            acc[0][0]=f2fma(a01.x,b0,acc[0][0]); acc[0][1]=f2fma(a01.x,b1,acc[0][1]);
            acc[0][2]=f2fma(a01.x,b2,acc[0][2]); acc[0][3]=f2fma(a01.x,b3,acc[0][3]);
            acc[1][0]=f2fma(a01.y,b0,acc[1][0]); acc[1][1]=f2fma(a01.y,b1,acc[1][1]);
            acc[1][2]=f2fma(a01.y,b2,acc[1][2]); acc[1][3]=f2fma(a01.y,b3,acc[1][3]);
            acc[2][0]=f2fma(a23.x,b0,acc[2][0]); acc[2][1]=f2fma(a23.x,b1,acc[2][1]);
            acc[2][2]=f2fma(a23.x,b2,acc[2][2]); acc[2][3]=f2fma(a23.x,b3,acc[2][3]);
            acc[3][0]=f2fma(a23.y,b0,acc[3][0]); acc[3][1]=f2fma(a23.y,b1,acc[3][1]);
            acc[3][2]=f2fma(a23.y,b2,acc[3][2]); acc[3][3]=f2fma(a23.y,b3,acc[3][3]);
        }
    }

    // epilogue: transpose to [px][o] in smem, then coalesced stores per o row
    __syncthreads();
    #pragma unroll
    for (int j=0;j<4;j++){
        #pragma unroll
        for (int q=0;q<4;q++){
            float lo,hi; upk2(acc[j][q],lo,hi);
            int o = tx*4+q, px = ty*8+2*j;
            sm[(size_t)px*65 + o]     = lo;
            sm[(size_t)(px+1)*65 + o] = hi;
        }
    }
    __syncthreads();
    {
        int w = t>>5, l = t&31;
        #pragma unroll
        for (int rr=0;rr<8;rr++){
            int o = w*8 + rr;
            float* op = out + ((size_t)(b*OO+o))*HWSZ + hw0;
            #pragma unroll
            for (int seg=0;seg<4;seg++){
                int px = seg*32 + l;
                op[px] = sm[(size_t)px*65 + o];
            }
        }
    }
}

// ---------------- launch ------------------------------------------------------
extern "C" void kernel_launch(void* const* d_in, const int* in_sizes, int n_in,
                              void* d_out, int out_size){
    const float* x        = (const float*)d_in[0];
    const float* w_main   = (const float*)d_in[1];
    const float* w_offset = (const float*)d_in[2];
    const float* b_offset = (const float*)d_in[3];
    const float* w_mask   = (const float*)d_in[4];
    const float* b_mask   = (const float*)d_in[5];
    float* out = (float*)d_out;

    int prep_n = CC*576 + CC*9*28;
    k_prep<<<(prep_n + TPB-1)/TPB, TPB>>>(w_main, w_offset, w_mask);
    dim3 gx(HWSZ/32, CC/32, BB);
    k_xt<<<gx, dim3(32,8)>>>(x);
    k_offmask<<<NPIX/TPB, TPB>>>(x, b_offset, b_mask);
    k_sample<<<NPIX/32, TPB>>>();
    k_gemm2<<<NPIX/128, TPB>>>(out);
}

// round 11
// speedup vs baseline: 1.1902x; 1.1902x over previous
#include <cuda_runtime.h>
#include <cuda_bf16.h>
#include <math.h>
#include <stdint.h>

#define BB 8
#define CC 64
#define OO 64
#define HH 128
#define WW 128
#define HWSZ (HH*WW)            // 16384
#define NPIX (BB*HWSZ)          // 131072
#define TPB 256

typedef unsigned long long ull;

// ---------------- scratch (allocation-free: __device__ globals) --------------
__device__ float          g_wom_t[CC*9*28];         // [c][t][j]
__device__ float4         g_cw4[(size_t)NPIX*9];    // per (p,k): 4 corner weights
__device__ int4           g_ci4[(size_t)NPIX*9];    // per (p,k): 4 clamped hw indices
__device__ float          g_xt[(size_t)NPIX*CC];    // [b][hw][c] (33.5 MB)
__device__ __nv_bfloat16  g_Shi[(size_t)9*NPIX*64]; // sampled hi: [k][p][c] 128B rows
__device__ __nv_bfloat16  g_Slo[(size_t)9*NPIX*64]; // sampled lo
__device__ __nv_bfloat16  g_Wbh[9*64*64];           // W hi: [k][o][c] 128B rows
__device__ __nv_bfloat16  g_Wbl[9*64*64];           // W lo

// ---------------- packed f32x2 helpers ---------------------------------------
__device__ __forceinline__ ull pk2(float lo, float hi){
    ull r; asm("mov.b64 %0, {%1,%2};" : "=l"(r) : "f"(lo), "f"(hi)); return r;
}
__device__ __forceinline__ void upk2(ull v, float& lo, float& hi){
    asm("mov.b64 {%0,%1}, %2;" : "=f"(lo), "=f"(hi) : "l"(v));
}
__device__ __forceinline__ ull f2fma(ull a, ull b, ull c){
    ull d; asm("fma.rn.f32x2 %0, %1, %2, %3;" : "=l"(d) : "l"(a), "l"(b), "l"(c)); return d;
}
__device__ __forceinline__ ull ldg2(const float* p){
    ull v; asm("ld.global.nc.b64 %0, [%1];" : "=l"(v) : "l"(p)); return v;
}
__device__ __forceinline__ uint32_t smem_u32(const void* p){
    uint32_t a;
    asm("{ .reg .u64 t; cvta.to.shared.u64 t, %1; cvt.u32.u64 %0, t; }" : "=r"(a) : "l"(p));
    return a;
}
__device__ __forceinline__ void ldsm4(uint32_t* r, uint32_t addr){
    asm volatile("ldmatrix.sync.aligned.m8n8.x4.shared.b16 {%0,%1,%2,%3}, [%4];"
        : "=r"(r[0]), "=r"(r[1]), "=r"(r[2]), "=r"(r[3]) : "r"(addr));
}
__device__ __forceinline__ void hmma(float* d, const uint32_t* a, uint32_t b0, uint32_t b1){
    asm volatile("mma.sync.aligned.m16n8k16.row.col.f32.bf16.bf16.f32 "
        "{%0,%1,%2,%3}, {%4,%5,%6,%7}, {%8,%9}, {%0,%1,%2,%3};"
        : "+f"(d[0]), "+f"(d[1]), "+f"(d[2]), "+f"(d[3])
        : "r"(a[0]), "r"(a[1]), "r"(a[2]), "r"(a[3]), "r"(b0), "r"(b1));
}

// ---------------- prep: W -> bf16 hi/lo [k][o][c]; offmask weights -----------
__global__ void k_prep(const float* __restrict__ wm,
                       const float* __restrict__ wo,
                       const float* __restrict__ wk){
    int i = blockIdx.x*TPB + threadIdx.x;
    if (i < 9*64*64){
        int k = i >> 12; int o = (i >> 6) & 63; int c = i & 63;
        float w = wm[(o*CC + c)*9 + k];
        __nv_bfloat16 h = __float2bfloat16(w);
        float r = w - __bfloat162float(h);
        g_Wbh[i] = h;
        g_Wbl[i] = __float2bfloat16(r);
    }
    int j2 = i - 9*64*64;
    if (j2 >= 0 && j2 < CC*9*28){
        int ct = j2/28; int j = j2 - ct*28; int c = ct/9; int t = ct - c*9;
        float v = 0.f;
        if (j < 18)      v = wo[(j*CC + c)*9 + t];
        else if (j < 27) v = wk[((j-18)*CC + c)*9 + t];
        g_wom_t[j2] = v;
    }
}

// ---------------- P0: x [b][c][hw] -> g_xt [b][hw][c] -------------------------
__global__ void k_xt(const float* __restrict__ x){
    __shared__ float t[32][33];
    int b  = blockIdx.z;
    int c0 = blockIdx.y*32;
    int hw0= blockIdx.x*32;
    const float* xb = x + ((size_t)b*CC + c0)*HWSZ + hw0;
    for (int i = threadIdx.y; i < 32; i += 8)
        t[i][threadIdx.x] = xb[(size_t)i*HWSZ + threadIdx.x];
    __syncthreads();
    float* xtb = g_xt + ((size_t)b*HWSZ + hw0)*CC + c0;
    for (int i = threadIdx.y; i < 32; i += 8)
        xtb[(size_t)i*CC + threadIdx.x] = t[threadIdx.x][i];
}

// ---- P1: offset(18)+mask(9) 3x3 conv; emit folded corner wgts/idx -----------
__global__ void __launch_bounds__(TPB)
k_offmask(const float* __restrict__ x,
          const float* __restrict__ boff,
          const float* __restrict__ bmsk){
    __shared__ __align__(16) float s_wom[32*9*28];

    int p   = blockIdx.x*TPB + threadIdx.x;
    int b   = p >> 14;
    int hw  = p & (HWSZ-1);
    int h   = hw >> 7;
    int wp  = hw & (WW-1);
    const float* xb = x + (size_t)b*CC*HWSZ;

    ull acc[14];
    #pragma unroll
    for (int q=0;q<14;q++){
        int j0=2*q, j1=2*q+1;
        float lo = (j0<18)? boff[j0] : (j0<27 ? bmsk[j0-18] : 0.f);
        float hi = (j1<18)? boff[j1] : (j1<27 ? bmsk[j1-18] : 0.f);
        acc[q] = pk2(lo,hi);
    }

    for (int cc=0; cc<CC; cc+=32){
        __syncthreads();
        for (int i=threadIdx.x; i<32*9*28; i+=TPB)
            s_wom[i] = g_wom_t[cc*9*28 + i];
        __syncthreads();

        for (int c=0;c<32;c++){
            const float* xc = xb + (cc+c)*HWSZ;
            float v[9];
            #pragma unroll
            for (int t=0;t<9;t++){
                int yy = h + t/3 - 1, xx = wp + t%3 - 1;
                v[t] = (yy>=0 && yy<HH && xx>=0 && xx<WW) ? __ldg(xc + yy*WW + xx) : 0.f;
            }
            #pragma unroll
            for (int t=0;t<9;t++){
                ull vv = pk2(v[t], v[t]);
                const ulonglong2* wq = (const ulonglong2*)&s_wom[(c*9+t)*28];
                #pragma unroll
                for (int q=0;q<7;q++){
                    ulonglong2 ww = wq[q];
                    acc[2*q]   = f2fma(vv, ww.x, acc[2*q]);
                    acc[2*q+1] = f2fma(vv, ww.y, acc[2*q+1]);
                }
            }
        }
    }

    #pragma unroll
    for (int k=0;k<9;k++){
        float dy, dx; upk2(acc[k], dy, dx);
        float mlo, mhi; upk2(acc[9 + k/2], mlo, mhi);
        float mraw = (k & 1) ? mhi : mlo;
        float mk = 1.f/(1.f + expf(-mraw));

        float py = dy + (float)(h + k/3 - 1);
        float px = dx + (float)(wp + k%3 - 1);
        float y0f = floorf(py), x0f = floorf(px);
        float ly = py - y0f, lx = px - x0f;
        int y0 = (int)y0f, x0 = (int)x0f;
        int y1 = y0 + 1,   x1 = x0 + 1;

        float vy0 = (y0>=0 && y0<HH) ? 1.f : 0.f;
        float vy1 = (y1>=0 && y1<HH) ? 1.f : 0.f;
        float vx0 = (x0>=0 && x0<WW) ? 1.f : 0.f;
        float vx1 = (x1>=0 && x1<WW) ? 1.f : 0.f;

        float w00 = (1.f-ly)*(1.f-lx)*vy0*vx0*mk;
        float w01 = (1.f-ly)*lx      *vy0*vx1*mk;
        float w10 = ly      *(1.f-lx)*vy1*vx0*mk;
        float w11 = ly      *lx      *vy1*vx1*mk;

        int y0c = min(max(y0,0),HH-1), y1c = min(max(y1,0),HH-1);
        int x0c = min(max(x0,0),WW-1), x1c = min(max(x1,0),WW-1);

        g_cw4[(size_t)p*9 + k] = make_float4(w00,w01,w10,w11);
        g_ci4[(size_t)p*9 + k] = make_int4(y0c*WW+x0c, y0c*WW+x1c,
                                           y1c*WW+x0c, y1c*WW+x1c);
    }
}

// ---- P2: sample -> bf16 hi/lo S[k][p][c] (128B rows, MMA-ready) --------------
__global__ void __launch_bounds__(TPB)
k_sample(){
    __shared__ float tile[64][33];

    int t  = threadIdx.x, w = t>>5, l = t&31;
    int p0 = blockIdx.x*32;
    int b  = p0 >> 14;
    const float* xtb = g_xt + (size_t)b*HWSZ*CC;

    for (int k=0;k<9;k++){
        __syncthreads();
        #pragma unroll
        for (int j=0;j<4;j++){
            int px = w*4 + j;
            size_t pk = (size_t)(p0+px)*9 + k;
            float4 wq = __ldg(&g_cw4[pk]);
            int4   iq = __ldg(&g_ci4[pk]);
            ull v;
            v = f2fma(pk2(wq.x,wq.x), ldg2(xtb + (size_t)iq.x*CC + 2*l), 0ull);
            v = f2fma(pk2(wq.y,wq.y), ldg2(xtb + (size_t)iq.y*CC + 2*l), v);
            v = f2fma(pk2(wq.z,wq.z), ldg2(xtb + (size_t)iq.z*CC + 2*l), v);
            v = f2fma(pk2(wq.w,wq.w), ldg2(xtb + (size_t)iq.w*CC + 2*l), v);
            float lo,hi; upk2(v,lo,hi);
            tile[2*l  ][px] = lo;
            tile[2*l+1][px] = hi;
        }
        __syncthreads();
        int px_w = t >> 3;            // 0..31
        int seg  = (t & 7) * 8;       // 0..56
        ushort hs[8], ls[8];
        #pragma unroll
        for (int i=0;i<8;i++){
            float f = tile[seg+i][px_w];
            __nv_bfloat16 h = __float2bfloat16(f);
            float r = f - __bfloat162float(h);
            __nv_bfloat16 lo_ = __float2bfloat16(r);
            hs[i] = *(ushort*)&h;
            ls[i] = *(ushort*)&lo_;
        }
        size_t row = ((size_t)k*NPIX + p0 + px_w)*64 + seg;
        *(uint4*)&g_Shi[row] = *(uint4*)hs;
        *(uint4*)&g_Slo[row] = *(uint4*)ls;
    }
}

// ---- P3: HMMA GEMM  out[p,o] = sum_{k,c} S[p][k,c] * W[o][k,c] --------------
// CTA = 128 px x 64 o; 8 warps, warp tile 32px x 32o. bf16 hi/lo, 3 passes,
// two-phase A staging (hi then lo in the same buffer) -> 36.9KB static smem.
// Smem rows padded to 144B (9 x 16B) -> conflict-free ldmatrix.
__global__ void __launch_bounds__(TPB)
k_mma(float* __restrict__ out){
    __shared__ __align__(16) uint4 smem[128*9 + 64*9 + 64*9];   // 36864 B
    uint4* sA  = smem;            // 128 rows x 9 uint4 (A hi OR A lo)
    uint4* sBh = smem + 128*9;    // 64 rows x 9
    uint4* sBl = sBh + 64*9;

    int t = threadIdx.x, l = t & 31, w = t >> 5;
    int p0 = blockIdx.x*128;
    int b  = p0 >> 14;
    int hw0= p0 & (HWSZ-1);

    int m0 = (w & 3)*32;     // pixel tile
    int n0 = (w >> 2)*32;    // output-channel tile

    uint32_t aBase  = smem_u32(smem);
    uint32_t bhBase = aBase + 128*9*16;
    uint32_t blBase = bhBase + 64*9*16;

    float acc[2][4][4];
    #pragma unroll
    for (int i=0;i<2;i++)
        #pragma unroll
        for (int j=0;j<4;j++)
            #pragma unroll
            for (int q=0;q<4;q++) acc[i][j][q] = 0.f;

    // per-lane ldmatrix row/k-half mapping (A and B fragments)
    int a_row = (l & 7) + ((l >> 3) & 1)*8;   // + m0 + mf*16
    int a_kb  = l >> 4;
    int b_row = (l & 7) + (l >> 4)*8;         // + n0 + nf2*16
    int b_kb  = (l >> 3) & 1;

    // load roles (rows are 128B = 8 uint4)
    int arow = t >> 1, ah4 = (t & 1)*4;       // A: 2 thr/row x 4 uint4
    int brow = t >> 2, bq2 = (t & 3)*2;       // B: 4 thr/row x 2 uint4

    for (int kc=0; kc<9; kc++){
        __syncthreads();
        // ---- phase 1 loads: A hi + B hi + B lo
        {
            const uint4* gA = (const uint4*)(g_Shi + ((size_t)kc*NPIX + p0 + arow)*64);
            #pragma unroll
            for (int u=0;u<4;u++) sA[arow*9 + ah4 + u] = __ldg(gA + ah4 + u);
            const uint4* gBh = (const uint4*)(g_Wbh + (size_t)kc*4096 + brow*64);
            const uint4* gBl = (const uint4*)(g_Wbl + (size_t)kc*4096 + brow*64);
            #pragma unroll
            for (int u=0;u<2;u++){
                sBh[brow*9 + bq2 + u] = __ldg(gBh + bq2 + u);
                sBl[brow*9 + bq2 + u] = __ldg(gBl + bq2 + u);
            }
        }
        __syncthreads();

        // ---- phase 1 MMA: hi*Bhi + hi*Blo
        #pragma unroll
        for (int ks=0; ks<4; ks++){
            uint32_t ah[2][4], bh[2][4], bl[2][4];
            #pragma unroll
            for (int mf=0; mf<2; mf++){
                uint32_t off = (uint32_t)((m0 + mf*16 + a_row)*9 + ks*2 + a_kb)*16u;
                ldsm4(ah[mf], aBase + off);
            }
            #pragma unroll
            for (int nf2=0; nf2<2; nf2++){
                uint32_t off = (uint32_t)((n0 + nf2*16 + b_row)*9 + ks*2 + b_kb)*16u;
                ldsm4(bh[nf2], bhBase + off);
                ldsm4(bl[nf2], blBase + off);
            }
            #pragma unroll
            for (int mf=0; mf<2; mf++){
                #pragma unroll
                for (int nf=0; nf<4; nf++){
                    uint32_t h0 = bh[nf>>1][(nf&1)*2], h1 = bh[nf>>1][(nf&1)*2+1];
                    uint32_t l0 = bl[nf>>1][(nf&1)*2], l1 = bl[nf>>1][(nf&1)*2+1];
                    hmma(acc[mf][nf], ah[mf], h0, h1);   // hi*hi
                    hmma(acc[mf][nf], ah[mf], l0, l1);   // hi*lo
                }
            }
        }
        __syncthreads();

        // ---- phase 2 loads: A lo into same buffer
        {
            const uint4* gA = (const uint4*)(g_Slo + ((size_t)kc*NPIX + p0 + arow)*64);
            #pragma unroll
            for (int u=0;u<4;u++) sA[arow*9 + ah4 + u] = __ldg(gA + ah4 + u);
        }
        __syncthreads();

        // ---- phase 2 MMA: lo*Bhi
        #pragma unroll
        for (int ks=0; ks<4; ks++){
            uint32_t al[2][4], bh[2][4];
            #pragma unroll
            for (int mf=0; mf<2; mf++){
                uint32_t off = (uint32_t)((m0 + mf*16 + a_row)*9 + ks*2 + a_kb)*16u;
                ldsm4(al[mf], aBase + off);
            }
            #pragma unroll
            for (int nf2=0; nf2<2; nf2++){
                uint32_t off = (uint32_t)((n0 + nf2*16 + b_row)*9 + ks*2 + b_kb)*16u;
                ldsm4(bh[nf2], bhBase + off);
            }
            #pragma unroll
            for (int mf=0; mf<2; mf++){
                #pragma unroll
                for (int nf=0; nf<4; nf++){
                    uint32_t h0 = bh[nf>>1][(nf&1)*2], h1 = bh[nf>>1][(nf&1)*2+1];
                    hmma(acc[mf][nf], al[mf], h0, h1);   // lo*hi
                }
            }
        }
    }

    // ---- epilogue: stage [o][px pad132] in smem, coalesced stores ------------
    __syncthreads();
    float* st = (float*)smem;    // 64*132*4 = 33792 B <= 36864
    {
        int group = l >> 2, tid4 = l & 3;
        #pragma unroll
        for (int mf=0; mf<2; mf++){
            int r0 = m0 + mf*16 + group;
            #pragma unroll
            for (int nf=0; nf<4; nf++){
                int o = n0 + nf*8 + 2*tid4;
                st[(size_t)o    *132 + r0    ] = acc[mf][nf][0];
                st[(size_t)(o+1)*132 + r0    ] = acc[mf][nf][1];
                st[(size_t)o    *132 + r0 + 8] = acc[mf][nf][2];
                st[(size_t)(o+1)*132 + r0 + 8] = acc[mf][nf][3];
            }
        }
    }
    __syncthreads();
    #pragma unroll
    for (int q=0;q<8;q++){
        int o = q*8 + w;
        float4 v = *(float4*)&st[(size_t)o*132 + 4*l];
        *(float4*)(out + ((size_t)(b*OO + o))*HWSZ + hw0 + 4*l) = v;
    }
}

// ---------------- launch ------------------------------------------------------
extern "C" void kernel_launch(void* const* d_in, const int* in_sizes, int n_in,
                              void* d_out, int out_size){
    const float* x        = (const float*)d_in[0];
    const float* w_main   = (const float*)d_in[1];
    const float* w_offset = (const float*)d_in[2];
    const float* b_offset = (const float*)d_in[3];
    const float* w_mask   = (const float*)d_in[4];
    const float* b_mask   = (const float*)d_in[5];
    float* out = (float*)d_out;

    int prep_n = 9*64*64 + CC*9*28;
    k_prep<<<(prep_n + TPB-1)/TPB, TPB>>>(w_main, w_offset, w_mask);
    dim3 gx(HWSZ/32, CC/32, BB);
    k_xt<<<gx, dim3(32,8)>>>(x);
    k_offmask<<<NPIX/TPB, TPB>>>(x, b_offset, b_mask);
    k_sample<<<NPIX/32, TPB>>>();
    k_mma<<<NPIX/128, TPB>>>(out);
}

// round 12
// speedup vs baseline: 1.3202x; 1.1093x over previous
#include <cuda_runtime.h>
#include <cuda_bf16.h>
#include <math.h>
#include <stdint.h>

#define BB 8
#define CC 64
#define OO 64
#define HH 128
#define WW 128
#define HWSZ (HH*WW)            // 16384
#define NPIX (BB*HWSZ)          // 131072
#define TPB 256

typedef unsigned long long ull;

// ---------------- scratch (allocation-free: __device__ globals) --------------
__device__ float          g_wom_t[CC*9*28];         // [c][t][j]
__device__ float4         g_cw4[(size_t)NPIX*9];    // per (p,k): 4 corner weights
__device__ int4           g_ci4[(size_t)NPIX*9];    // per (p,k): 4 clamped hw indices
__device__ float          g_xt[(size_t)NPIX*CC];    // [b][hw][c] (33.5 MB, L2-resident)
__device__ __nv_bfloat16  g_Wbh[9*64*64];           // W hi: [k][o][c] 128B rows
__device__ __nv_bfloat16  g_Wbl[9*64*64];           // W lo

// ---------------- packed f32x2 helpers ---------------------------------------
__device__ __forceinline__ ull pk2(float lo, float hi){
    ull r; asm("mov.b64 %0, {%1,%2};" : "=l"(r) : "f"(lo), "f"(hi)); return r;
}
__device__ __forceinline__ void upk2(ull v, float& lo, float& hi){
    asm("mov.b64 {%0,%1}, %2;" : "=f"(lo), "=f"(hi) : "l"(v));
}
__device__ __forceinline__ ull f2fma(ull a, ull b, ull c){
    ull d; asm("fma.rn.f32x2 %0, %1, %2, %3;" : "=l"(d) : "l"(a), "l"(b), "l"(c)); return d;
}
__device__ __forceinline__ ull ldg2(const float* p){
    ull v; asm("ld.global.nc.b64 %0, [%1];" : "=l"(v) : "l"(p)); return v;
}
__device__ __forceinline__ uint32_t smem_u32(const void* p){
    uint32_t a;
    asm("{ .reg .u64 t; cvta.to.shared.u64 t, %1; cvt.u32.u64 %0, t; }" : "=r"(a) : "l"(p));
    return a;
}
__device__ __forceinline__ void ldsm4(uint32_t* r, uint32_t addr){
    asm volatile("ldmatrix.sync.aligned.m8n8.x4.shared.b16 {%0,%1,%2,%3}, [%4];"
        : "=r"(r[0]), "=r"(r[1]), "=r"(r[2]), "=r"(r[3]) : "r"(addr));
}
__device__ __forceinline__ void hmma(float* d, const uint32_t* a, uint32_t b0, uint32_t b1){
    asm volatile("mma.sync.aligned.m16n8k16.row.col.f32.bf16.bf16.f32 "
        "{%0,%1,%2,%3}, {%4,%5,%6,%7}, {%8,%9}, {%0,%1,%2,%3};"
        : "+f"(d[0]), "+f"(d[1]), "+f"(d[2]), "+f"(d[3])
        : "r"(a[0]), "r"(a[1]), "r"(a[2]), "r"(a[3]), "r"(b0), "r"(b1));
}

// ---------------- prep: W -> bf16 hi/lo [k][o][c]; offmask weights -----------
__global__ void k_prep(const float* __restrict__ wm,
                       const float* __restrict__ wo,
                       const float* __restrict__ wk){
    int i = blockIdx.x*TPB + threadIdx.x;
    if (i < 9*64*64){
        int k = i >> 12; int o = (i >> 6) & 63; int c = i & 63;
        float w = wm[(o*CC + c)*9 + k];
        __nv_bfloat16 h = __float2bfloat16(w);
        float r = w - __bfloat162float(h);
        g_Wbh[i] = h;
        g_Wbl[i] = __float2bfloat16(r);
    }
    int j2 = i - 9*64*64;
    if (j2 >= 0 && j2 < CC*9*28){
        int ct = j2/28; int j = j2 - ct*28; int c = ct/9; int t = ct - c*9;
        float v = 0.f;
        if (j < 18)      v = wo[(j*CC + c)*9 + t];
        else if (j < 27) v = wk[((j-18)*CC + c)*9 + t];
        g_wom_t[j2] = v;
    }
}

// ---------------- P0: x [b][c][hw] -> g_xt [b][hw][c] -------------------------
__global__ void k_xt(const float* __restrict__ x){
    __shared__ float t[32][33];
    int b  = blockIdx.z;
    int c0 = blockIdx.y*32;
    int hw0= blockIdx.x*32;
    const float* xb = x + ((size_t)b*CC + c0)*HWSZ + hw0;
    for (int i = threadIdx.y; i < 32; i += 8)
        t[i][threadIdx.x] = xb[(size_t)i*HWSZ + threadIdx.x];
    __syncthreads();
    float* xtb = g_xt + ((size_t)b*HWSZ + hw0)*CC + c0;
    for (int i = threadIdx.y; i < 32; i += 8)
        xtb[(size_t)i*CC + threadIdx.x] = t[threadIdx.x][i];
}

// ---- P1: offset(18)+mask(9) 3x3 conv; emit folded corner wgts/idx -----------
__global__ void __launch_bounds__(TPB)
k_offmask(const float* __restrict__ x,
          const float* __restrict__ boff,
          const float* __restrict__ bmsk){
    __shared__ __align__(16) float s_wom[32*9*28];

    int p   = blockIdx.x*TPB + threadIdx.x;
    int b   = p >> 14;
    int hw  = p & (HWSZ-1);
    int h   = hw >> 7;
    int wp  = hw & (WW-1);
    const float* xb = x + (size_t)b*CC*HWSZ;

    ull acc[14];
    #pragma unroll
    for (int q=0;q<14;q++){
        int j0=2*q, j1=2*q+1;
        float lo = (j0<18)? boff[j0] : (j0<27 ? bmsk[j0-18] : 0.f);
        float hi = (j1<18)? boff[j1] : (j1<27 ? bmsk[j1-18] : 0.f);
        acc[q] = pk2(lo,hi);
    }

    for (int cc=0; cc<CC; cc+=32){
        __syncthreads();
        for (int i=threadIdx.x; i<32*9*28; i+=TPB)
            s_wom[i] = g_wom_t[cc*9*28 + i];
        __syncthreads();

        for (int c=0;c<32;c++){
            const float* xc = xb + (cc+c)*HWSZ;
            float v[9];
            #pragma unroll
            for (int t=0;t<9;t++){
                int yy = h + t/3 - 1, xx = wp + t%3 - 1;
                v[t] = (yy>=0 && yy<HH && xx>=0 && xx<WW) ? __ldg(xc + yy*WW + xx) : 0.f;
            }
            #pragma unroll
            for (int t=0;t<9;t++){
                ull vv = pk2(v[t], v[t]);
                const ulonglong2* wq = (const ulonglong2*)&s_wom[(c*9+t)*28];
                #pragma unroll
                for (int q=0;q<7;q++){
                    ulonglong2 ww = wq[q];
                    acc[2*q]   = f2fma(vv, ww.x, acc[2*q]);
                    acc[2*q+1] = f2fma(vv, ww.y, acc[2*q+1]);
                }
            }
        }
    }

    #pragma unroll
    for (int k=0;k<9;k++){
        float dy, dx; upk2(acc[k], dy, dx);
        float mlo, mhi; upk2(acc[9 + k/2], mlo, mhi);
        float mraw = (k & 1) ? mhi : mlo;
        float mk = 1.f/(1.f + expf(-mraw));

        float py = dy + (float)(h + k/3 - 1);
        float px = dx + (float)(wp + k%3 - 1);
        float y0f = floorf(py), x0f = floorf(px);
        float ly = py - y0f, lx = px - x0f;
        int y0 = (int)y0f, x0 = (int)x0f;
        int y1 = y0 + 1,   x1 = x0 + 1;

        float vy0 = (y0>=0 && y0<HH) ? 1.f : 0.f;
        float vy1 = (y1>=0 && y1<HH) ? 1.f : 0.f;
        float vx0 = (x0>=0 && x0<WW) ? 1.f : 0.f;
        float vx1 = (x1>=0 && x1<WW) ? 1.f : 0.f;

        float w00 = (1.f-ly)*(1.f-lx)*vy0*vx0*mk;
        float w01 = (1.f-ly)*lx      *vy0*vx1*mk;
        float w10 = ly      *(1.f-lx)*vy1*vx0*mk;
        float w11 = ly      *lx      *vy1*vx1*mk;

        int y0c = min(max(y0,0),HH-1), y1c = min(max(y1,0),HH-1);
        int x0c = min(max(x0,0),WW-1), x1c = min(max(x1,0),WW-1);

        g_cw4[(size_t)p*9 + k] = make_float4(w00,w01,w10,w11);
        g_ci4[(size_t)p*9 + k] = make_int4(y0c*WW+x0c, y0c*WW+x1c,
                                           y1c*WW+x0c, y1c*WW+x1c);
    }
}

// ---- P2: fused gather + HMMA GEMM -------------------------------------------
// CTA = 64 px x 64 o, 8 warps (warp tile 32px x 16o). Per k-tap: warps gather
// 8 px each from L2-resident x_t (coalesced 256B rows), convert to bf16 hi/lo
// in registers, write packed pairs into ldmatrix-ready smem (144B rows), then
// 3-pass HMMA (hi*hi + hi*lo + lo*hi). No S tensor, no DRAM round-trip.
__global__ void __launch_bounds__(TPB)
k_fuse(float* __restrict__ out){
    __shared__ __align__(16) uint4 smem[4*576];   // Ahi|Alo|Bh|Bl, 36864 B
    uint4* sBh = smem + 2*576;
    uint4* sBl = smem + 3*576;
    uint32_t* wAhi = (uint32_t*)smem;             // word view for gather writes
    uint32_t* wAlo = (uint32_t*)(smem + 576);

    int t = threadIdx.x, l = t & 31, w = t >> 5;
    int p0 = blockIdx.x*64;
    int b  = p0 >> 14;
    int hw0= p0 & (HWSZ-1);
    const float* xtb = g_xt + (size_t)b*HWSZ*CC;

    int m0 = (w & 1)*32;      // pixel tile (2 m-tiles of 32)
    int n0 = (w >> 1)*16;     // o tile (4 n-tiles of 16)

    uint32_t aBase  = smem_u32(smem);
    uint32_t alBase = aBase + 576*16;
    uint32_t bhBase = aBase + 2*576*16;
    uint32_t blBase = aBase + 3*576*16;

    float acc[2][2][4];
    #pragma unroll
    for (int i=0;i<2;i++)
        #pragma unroll
        for (int j=0;j<2;j++)
            #pragma unroll
            for (int q=0;q<4;q++) acc[i][j][q] = 0.f;

    // ldmatrix lane mappings
    int a_row = (l & 7) + ((l >> 3) & 1)*8;   // + m0 + mf*16
    int a_kb  = l >> 4;
    int b_row = (l & 7) + (l >> 4)*8;         // + n0
    int b_kb  = (l >> 3) & 1;

    // B load roles (rows are 128B = 8 uint4, strided to 9)
    int brow = t >> 2, bq2 = (t & 3)*2;

    for (int kc=0; kc<9; kc++){
        __syncthreads();   // protect smem reuse from previous iteration's mma
        // ---- gather 8 px per warp; lane handles channels 2l, 2l+1
        #pragma unroll
        for (int j=0;j<8;j++){
            int px = w*8 + j;
            size_t pk = (size_t)(p0+px)*9 + kc;
            float4 wq = __ldg(&g_cw4[pk]);
            int4   iq = __ldg(&g_ci4[pk]);
            ull v;
            v = f2fma(pk2(wq.x,wq.x), ldg2(xtb + (size_t)iq.x*CC + 2*l), 0ull);
            v = f2fma(pk2(wq.y,wq.y), ldg2(xtb + (size_t)iq.y*CC + 2*l), v);
            v = f2fma(pk2(wq.z,wq.z), ldg2(xtb + (size_t)iq.z*CC + 2*l), v);
            v = f2fma(pk2(wq.w,wq.w), ldg2(xtb + (size_t)iq.w*CC + 2*l), v);
            float f0, f1; upk2(v, f0, f1);
            __nv_bfloat16 h0 = __float2bfloat16(f0);
            __nv_bfloat16 h1 = __float2bfloat16(f1);
            float r0 = f0 - __bfloat162float(h0);
            float r1 = f1 - __bfloat162float(h1);
            __nv_bfloat16 e0 = __float2bfloat16(r0);
            __nv_bfloat16 e1 = __float2bfloat16(r1);
            uint32_t ph = ((uint32_t)*(ushort*)&h1 << 16) | *(ushort*)&h0;
            uint32_t pl = ((uint32_t)*(ushort*)&e1 << 16) | *(ushort*)&e0;
            wAhi[px*36 + l] = ph;     // 144B rows -> conflict-free
            wAlo[px*36 + l] = pl;
        }
        // ---- load B hi/lo (128B rows -> 9-uint4 stride)
        {
            const uint4* gBh = (const uint4*)(g_Wbh + (size_t)kc*4096 + brow*64);
            const uint4* gBl = (const uint4*)(g_Wbl + (size_t)kc*4096 + brow*64);
            #pragma unroll
            for (int u=0;u<2;u++){
                sBh[brow*9 + bq2 + u] = __ldg(gBh + bq2 + u);
                sBl[brow*9 + bq2 + u] = __ldg(gBl + bq2 + u);
            }
        }
        __syncthreads();

        // ---- HMMA: 3 passes in one loop (Ahi & Alo both resident)
        #pragma unroll
        for (int ks=0; ks<4; ks++){
            uint32_t ah[2][4], al[2][4], bh[4], bl[4];
            #pragma unroll
            for (int mf=0; mf<2; mf++){
                uint32_t off = (uint32_t)((m0 + mf*16 + a_row)*9 + ks*2 + a_kb)*16u;
                ldsm4(ah[mf], aBase  + off);
                ldsm4(al[mf], alBase + off);
            }
            {
                uint32_t off = (uint32_t)((n0 + b_row)*9 + ks*2 + b_kb)*16u;
                ldsm4(bh, bhBase + off);
                ldsm4(bl, blBase + off);
            }
            #pragma unroll
            for (int mf=0; mf<2; mf++){
                #pragma unroll
                for (int nf=0; nf<2; nf++){
                    uint32_t h0 = bh[nf*2], h1 = bh[nf*2+1];
                    uint32_t l0 = bl[nf*2], l1 = bl[nf*2+1];
                    hmma(acc[mf][nf], ah[mf], h0, h1);   // hi*hi
                    hmma(acc[mf][nf], ah[mf], l0, l1);   // hi*lo
                    hmma(acc[mf][nf], al[mf], h0, h1);   // lo*hi
                }
            }
        }
    }

    // ---- epilogue: stage [o][px pad68] in smem, coalesced float4 stores ------
    __syncthreads();
    float* st = (float*)smem;   // 64*68*4 = 17408 B
    {
        int group = l >> 2, tid4 = l & 3;
        #pragma unroll
        for (int mf=0; mf<2; mf++){
            int r0 = m0 + mf*16 + group;
            #pragma unroll
            for (int nf=0; nf<2; nf++){
                int o = n0 + nf*8 + 2*tid4;
                st[(size_t)o    *68 + r0    ] = acc[mf][nf][0];
                st[(size_t)(o+1)*68 + r0    ] = acc[mf][nf][1];
                st[(size_t)o    *68 + r0 + 8] = acc[mf][nf][2];
                st[(size_t)(o+1)*68 + r0 + 8] = acc[mf][nf][3];
            }
        }
    }
    __syncthreads();
    #pragma unroll
    for (int q=0;q<4;q++){
        int o   = q*16 + w*2 + (l >> 4);
        int px4 = (l & 15)*4;
        float4 v = *(float4*)&st[(size_t)o*68 + px4];
        *(float4*)(out + ((size_t)(b*OO + o))*HWSZ + hw0 + px4) = v;
    }
}

// ---------------- launch ------------------------------------------------------
extern "C" void kernel_launch(void* const* d_in, const int* in_sizes, int n_in,
                              void* d_out, int out_size){
    const float* x        = (const float*)d_in[0];
    const float* w_main   = (const float*)d_in[1];
    const float* w_offset = (const float*)d_in[2];
    const float* b_offset = (const float*)d_in[3];
    const float* w_mask   = (const float*)d_in[4];
    const float* b_mask   = (const float*)d_in[5];
    float* out = (float*)d_out;

    int prep_n = 9*64*64 + CC*9*28;
    k_prep<<<(prep_n + TPB-1)/TPB, TPB>>>(w_main, w_offset, w_mask);
    dim3 gx(HWSZ/32, CC/32, BB);
    k_xt<<<gx, dim3(32,8)>>>(x);
    k_offmask<<<NPIX/TPB, TPB>>>(x, b_offset, b_mask);
    k_fuse<<<NPIX/64, TPB>>>(out);
}